// round 1
// baseline (speedup 1.0000x reference)
#include <cuda_runtime.h>
#include <cstdint>

#define C_CH 32
#define DIM  128
#define NK   27
#define VOL_ELEMS (C_CH * DIM * DIM * DIM)

// Scratch (device globals: allocation-free per harness rules)
__device__ float g_vol[VOL_ELEMS];        // channel-last [z][y][x][c]
__device__ float g_G[NK * C_CH * C_CH];   // [k][j][o] folded weight tensor
__device__ float g_bias[C_CH];

// ---------------------------------------------------------------------------
// Kernel 1: fold all linear layers into G[k][j][o] and bias[o].
// out[n,o] = sum_{k,j} feats[n,k,j] * G[k,j,o] + bias[o]
// ---------------------------------------------------------------------------
__global__ __launch_bounds__(1024) void prep_kernel(
    const float* __restrict__ w_d1, const float* __restrict__ b_d1,
    const float* __restrict__ w_d2, const float* __restrict__ b_d2,
    const float* __restrict__ w_c1, const float* __restrict__ b_c1,
    const float* __restrict__ w_c2, const float* __restrict__ b_c2,
    const float* __restrict__ conv_w, const float* __restrict__ conv_b)
{
    __shared__ float Wd[1024], Wc[1024], bd[32], bc[32];
    const int tid = threadIdx.x;

    {   // composite linears: Wd = w_d2 @ w_d1, Wc = w_c2 @ w_c1
        const int i = tid >> 5, j = tid & 31;
        float sd = 0.f, sc = 0.f;
        #pragma unroll
        for (int m = 0; m < 32; m++) {
            sd += w_d2[i * 32 + m] * w_d1[m * 32 + j];
            sc += w_c2[i * 32 + m] * w_c1[m * 32 + j];
        }
        Wd[tid] = sd; Wc[tid] = sc;
    }
    if (tid < 32) {
        float sd = 0.f, sc = 0.f;
        #pragma unroll
        for (int m = 0; m < 32; m++) {
            sd += w_d2[tid * 32 + m] * b_d1[m];
            sc += w_c2[tid * 32 + m] * b_c1[m];
        }
        bd[tid] = sd + b_d2[tid];
        bc[tid] = sc + b_c2[tid];
    }
    __syncthreads();

    // M[o][j][k] = sum_c conv_w[o][c][k] * Wd[c][j], stored as g_G[k*1024 + j*32 + o]
    for (int idx = tid; idx < NK * 1024; idx += 1024) {
        const int o = idx & 31, j = (idx >> 5) & 31, k = idx >> 10;
        float s = 0.f;
        #pragma unroll
        for (int c = 0; c < 32; c++)
            s += conv_w[(o * 32 + c) * 27 + k] * Wd[c * 32 + j];
        g_G[idx] = s;
    }
    __syncthreads();

    // center-tap correction on the k=13 plane:
    //   G[13][j][o] += Wc[o][j] - sum_k M[o][j][k]
    {
        const int o = tid & 31, j = tid >> 5;
        float S = 0.f;
        #pragma unroll
        for (int k = 0; k < NK; k++) S += g_G[k * 1024 + tid];
        g_G[13 * 1024 + tid] += Wc[o * 32 + j] - S;
    }
    if (tid < 32) {
        // bias[o] = sum_{k,c} bd[c]*conv_w[o][c][k] + conv_b[o] + bc[o]
        float acc = 0.f;
        #pragma unroll
        for (int c = 0; c < 32; c++) {
            float rs = 0.f;
            #pragma unroll
            for (int k = 0; k < 27; k++) rs += conv_w[(tid * 32 + c) * 27 + k];
            acc += bd[c] * rs;
        }
        g_bias[tid] = acc + conv_b[tid] + bc[tid];
    }
}

// ---------------------------------------------------------------------------
// Kernel 2: transpose voxel volume [C][D][H][W] -> channel-last [D][H][W][C]
// so each trilinear corner fetch (32 channels) is one contiguous 128B line.
// ---------------------------------------------------------------------------
__global__ __launch_bounds__(256) void transpose_kernel(const float* __restrict__ vin)
{
    __shared__ float tile[32][33];
    const int x0 = blockIdx.x * 32;
    const int y = blockIdx.y, z = blockIdx.z;
    const int tx = threadIdx.x, ty = threadIdx.y;  // 32 x 8

    #pragma unroll
    for (int i = 0; i < 4; i++) {
        const int c = ty + 8 * i;
        tile[c][tx] = vin[(((size_t)c * DIM + z) * DIM + y) * DIM + x0 + tx];
    }
    __syncthreads();
    const size_t obase = ((size_t)z * DIM + y) * DIM + x0;
    #pragma unroll
    for (int i = 0; i < 4; i++) {
        const int xx = ty + 8 * i;
        g_vol[(obase + xx) * C_CH + tx] = tile[tx][xx];
    }
}

// ---------------------------------------------------------------------------
// Kernel 3: fused sample + GEMM.
// One warp handles 16 vertices. lane = channel during sampling, lane = output
// channel during the reduction. f staged in smem [c][v] (stride 18), reduced
// with packed fma.rn.f32x2 (2 MACs/instr, a pattern ptxas won't auto-fuse).
// ---------------------------------------------------------------------------
__global__ __launch_bounds__(256) void main_kernel(
    const float* __restrict__ verts, float* __restrict__ out, int Ntot)
{
    __shared__ float fs[8 * 32 * 18];
    const int warp = threadIdx.x >> 5, lane = threadIdx.x & 31;
    const int nTiles = (Ntot + 15) >> 4;
    const int tile = blockIdx.x * 8 + warp;
    if (tile >= nTiles) return;

    const int n0 = tile * 16;
    const int v = lane & 15;             // lanes 16-31 mirror lanes 0-15
    const int n = n0 + v;
    const bool valid = (n < Ntot);

    float gxv = 0.f, gyv = 0.f, gzv = 0.f;   // normalized coords of my vertex
    if (valid) {
        gxv = verts[3 * n + 0];
        gyv = verts[3 * n + 1];
        gzv = verts[3 * n + 2];
    }

    float* fw = fs + warp * (32 * 18);
    unsigned long long acc2[8];
    #pragma unroll
    for (int i = 0; i < 8; i++) acc2[i] = 0ull;

    const float SH = 0.0625f;   // 2^(STEPS+1-STEP)/128

    for (int k = 0; k < NK; k++) {
        // --- per-lane geometry for my own vertex (no 32x redundancy) ---
        const int ki = k / 9, kj = (k / 3) % 3, kl = k % 3;
        float gx = gxv + (float)(ki - 1) * SH;
        float gy = gyv + (float)(kj - 1) * SH;
        float gz = gzv + (float)(kl - 1) * SH;
        // align_corners=True, border clamp: p = clip((g+1)*0.5*127, 0, 127)
        float px = fminf(fmaxf((gx + 1.f) * 63.5f, 0.f), 127.f);
        float py = fminf(fmaxf((gy + 1.f) * 63.5f, 0.f), 127.f);
        float pz = fminf(fmaxf((gz + 1.f) * 63.5f, 0.f), 127.f);
        const float fx = floorf(px), fy = floorf(py), fz = floorf(pz);
        const int ix = (int)fx, iy = (int)fy, iz = (int)fz;
        const float wx = px - fx, wy = py - fy, wz = pz - fz;
        const int base = iz * (DIM * DIM * C_CH) + iy * (DIM * C_CH) + ix * C_CH;
        const int sx = (ix < DIM - 1) ? C_CH : 0;
        const int sy = (iy < DIM - 1) ? DIM * C_CH : 0;
        const int sz = (iz < DIM - 1) ? DIM * DIM * C_CH : 0;

        // --- warp-cooperative sampling: broadcast geometry, lane = channel ---
        #pragma unroll
        for (int vv = 0; vv < 16; vv++) {
            const int b   = __shfl_sync(0xffffffffu, base, vv);
            const int sxv = __shfl_sync(0xffffffffu, sx, vv);
            const int syv = __shfl_sync(0xffffffffu, sy, vv);
            const int szv = __shfl_sync(0xffffffffu, sz, vv);
            const float wxv = __shfl_sync(0xffffffffu, wx, vv);
            const float wyv = __shfl_sync(0xffffffffu, wy, vv);
            const float wzv = __shfl_sync(0xffffffffu, wz, vv);
            const float* p = g_vol + b + lane;
            const float f000 = __ldg(p);
            const float f001 = __ldg(p + sxv);
            const float f010 = __ldg(p + syv);
            const float f011 = __ldg(p + syv + sxv);
            const float f100 = __ldg(p + szv);
            const float f101 = __ldg(p + szv + sxv);
            const float f110 = __ldg(p + szv + syv);
            const float f111 = __ldg(p + szv + syv + sxv);
            const float a0 = f000 + wxv * (f001 - f000);
            const float a1 = f010 + wxv * (f011 - f010);
            const float a2 = f100 + wxv * (f101 - f100);
            const float a3 = f110 + wxv * (f111 - f110);
            const float b0 = a0 + wyv * (a1 - a0);
            const float b1 = a2 + wyv * (a3 - a2);
            fw[lane * 18 + vv] = b0 + wzv * (b1 - b0);
        }
        __syncwarp();

        // --- reduction: acc[v][lane] += f[v][c] * G[k][c][lane], packed 2/v ---
        #pragma unroll 4
        for (int c = 0; c < 32; c++) {
            const float g = __ldg(&g_G[k * 1024 + c * 32 + lane]);
            unsigned long long g2;
            asm("mov.b64 %0, {%1, %1};" : "=l"(g2) : "r"(__float_as_uint(g)));
            const unsigned long long* fq =
                reinterpret_cast<const unsigned long long*>(fw + c * 18);
            #pragma unroll
            for (int v2 = 0; v2 < 8; v2++) {
                asm("fma.rn.f32x2 %0, %1, %2, %0;"
                    : "+l"(acc2[v2]) : "l"(fq[v2]), "l"(g2));
            }
        }
        __syncwarp();
    }

    const float bias = __ldg(&g_bias[lane]);
    #pragma unroll
    for (int v2 = 0; v2 < 8; v2++) {
        const float lo = __uint_as_float((unsigned)(acc2[v2] & 0xffffffffull));
        const float hi = __uint_as_float((unsigned)(acc2[v2] >> 32));
        const int na = n0 + 2 * v2, nb = na + 1;
        if (na < Ntot) out[na * C_CH + lane] = lo + bias;
        if (nb < Ntot) out[nb * C_CH + lane] = hi + bias;
    }
}

// ---------------------------------------------------------------------------
extern "C" void kernel_launch(void* const* d_in, const int* in_sizes, int n_in,
                              void* d_out, int out_size)
{
    const float* voxel = (const float*)d_in[0];
    const float* verts = (const float*)d_in[1];
    const int Ntot = in_sizes[1] / 3;

    prep_kernel<<<1, 1024>>>(
        (const float*)d_in[2], (const float*)d_in[3],
        (const float*)d_in[4], (const float*)d_in[5],
        (const float*)d_in[6], (const float*)d_in[7],
        (const float*)d_in[8], (const float*)d_in[9],
        (const float*)d_in[10], (const float*)d_in[11]);

    dim3 tb(32, 8);
    dim3 tg(DIM / 32, DIM, DIM);
    transpose_kernel<<<tg, tb>>>(voxel);

    const int nTiles = (Ntot + 15) / 16;
    const int blocks = (nTiles + 7) / 8;
    main_kernel<<<blocks, 256>>>(verts, (float*)d_out, Ntot);
}

// round 2
// speedup vs baseline: 2.4113x; 2.4113x over previous
#include <cuda_runtime.h>
#include <cstdint>

#define C_CH 32
#define DIM  128
#define NK   27
#define VOL_ELEMS (C_CH * DIM * DIM * DIM)

// Scratch (device globals: allocation-free per harness rules)
__device__ float g_vol[VOL_ELEMS];        // channel-last [z][y][x][c]
__device__ float g_G[NK * C_CH * C_CH];   // [k][j][o] folded weight tensor
__device__ float g_bias[C_CH];

// ---------------------------------------------------------------------------
// Prep 1 (27 blocks, one per neighbour k): M[k][j][o] = sum_c conv_w[o,c,k]*Wd[c,j]
// conv_w k-slice staged transposed in smem so the inner reads are conflict-free
// and spread across 27 SMs (the single-SM 32-way-replay disaster of R1's prep).
// ---------------------------------------------------------------------------
__global__ __launch_bounds__(1024) void prep1_kernel(
    const float* __restrict__ w_d1, const float* __restrict__ w_d2,
    const float* __restrict__ conv_w)
{
    __shared__ float Wds[1024];    // Wd[c][j]
    __shared__ float convs[1024];  // conv[c][o] for this k
    const int tid = threadIdx.x, k = blockIdx.x;
    const int o = tid & 31, j = tid >> 5;   // also (i=j, jj=o) for Wd compute

    {   // Wd = w_d2 @ w_d1 (redundant per block; trivial)
        float s = 0.f;
        #pragma unroll
        for (int m = 0; m < 32; m++)
            s += w_d2[(tid >> 5) * 32 + m] * w_d1[m * 32 + (tid & 31)];
        Wds[tid] = s;
    }
    // stage conv slice: convs[c*32+o] = conv_w[(o*32+c)*27+k]; tid = c*32+o
    convs[tid] = conv_w[(o * 32 + (tid >> 5)) * 27 + k];
    __syncthreads();

    float acc = 0.f;
    #pragma unroll
    for (int c = 0; c < 32; c++)
        acc += convs[c * 32 + o] * Wds[c * 32 + j];   // o: conflict-free, j: broadcast
    g_G[k * 1024 + j * 32 + o] = acc;
}

// ---------------------------------------------------------------------------
// Prep 2 (1 block): center-tap correction on the k=13 plane + fused bias.
// ---------------------------------------------------------------------------
__global__ __launch_bounds__(1024) void prep2_kernel(
    const float* __restrict__ w_d2, const float* __restrict__ b_d1,
    const float* __restrict__ b_d2,
    const float* __restrict__ w_c1, const float* __restrict__ b_c1,
    const float* __restrict__ w_c2, const float* __restrict__ b_c2,
    const float* __restrict__ conv_w, const float* __restrict__ conv_b)
{
    __shared__ float Wcs[1024], part[1024], bds[32], bcs[32];
    const int tid = threadIdx.x;
    const int o = tid & 31, j = tid >> 5;

    {   // Wc = w_c2 @ w_c1
        float s = 0.f;
        #pragma unroll
        for (int m = 0; m < 32; m++)
            s += w_c2[(tid >> 5) * 32 + m] * w_c1[m * 32 + (tid & 31)];
        Wcs[tid] = s;
    }
    if (tid < 32) {
        float sd = 0.f, sc = 0.f;
        #pragma unroll
        for (int m = 0; m < 32; m++) {
            sd += w_d2[tid * 32 + m] * b_d1[m];
            sc += w_c2[tid * 32 + m] * b_c1[m];
        }
        bds[tid] = sd + b_d2[tid];
        bcs[tid] = sc + b_c2[tid];
    }
    // rs[o][c] = sum_k conv_w[o,c,k]  (27 contiguous floats per thread)
    float rs = 0.f;
    #pragma unroll
    for (int k = 0; k < NK; k++)
        rs += conv_w[(o * 32 + j) * 27 + k];
    __syncthreads();

    part[j * 32 + o] = bds[j] * rs;   // part[c][o] = bd[c]*rs[o][c]

    // center correction: G[13][j][o] += Wc[o][j] - sum_k M[o][j][k]
    float S = 0.f;
    #pragma unroll
    for (int k = 0; k < NK; k++) S += g_G[k * 1024 + tid];
    g_G[13 * 1024 + tid] += Wcs[o * 32 + j] - S;
    __syncthreads();

    if (tid < 32) {
        float a = 0.f;
        #pragma unroll
        for (int c = 0; c < 32; c++) a += part[c * 32 + tid];
        g_bias[tid] = a + conv_b[tid] + bcs[tid];
    }
}

// ---------------------------------------------------------------------------
// Transpose voxel volume [C][D][H][W] -> channel-last [D][H][W][C].
// ---------------------------------------------------------------------------
__global__ __launch_bounds__(256) void transpose_kernel(const float* __restrict__ vin)
{
    __shared__ float tile[32][33];
    const int x0 = blockIdx.x * 32;
    const int y = blockIdx.y, z = blockIdx.z;
    const int tx = threadIdx.x, ty = threadIdx.y;  // 32 x 8

    #pragma unroll
    for (int i = 0; i < 4; i++) {
        const int c = ty + 8 * i;
        tile[c][tx] = vin[(((size_t)c * DIM + z) * DIM + y) * DIM + x0 + tx];
    }
    __syncthreads();
    const size_t obase = ((size_t)z * DIM + y) * DIM + x0;
    #pragma unroll
    for (int i = 0; i < 4; i++) {
        const int xx = ty + 8 * i;
        g_vol[(obase + xx) * C_CH + tx] = tile[tx][xx];
    }
}

// ---------------------------------------------------------------------------
// Fused sample + GEMM. One warp = 16 vertices.
// Sampling: lane = (vertex-quad v4, channel-quad c4); corners fetched as
// float4 (LDG.128), trilinear via 8 precomputed corner weights. Results
// stored transposed into smem f[c][v]. Reduction: lane = output channel,
// packed fma.rn.f32x2 over vertex pairs.
// ---------------------------------------------------------------------------
__global__ __launch_bounds__(256) void main_kernel(
    const float* __restrict__ verts, float* __restrict__ out, int Ntot)
{
    __shared__ float fs[8 * 32 * 18];
    const int warp = threadIdx.x >> 5, lane = threadIdx.x & 31;
    const int nTiles = (Ntot + 15) >> 4;
    const int tile = blockIdx.x * 8 + warp;
    if (tile >= nTiles) return;

    const int n0 = tile * 16;
    const int v = lane & 15;             // geometry vertex (upper half mirrors)
    const int n = n0 + v;
    const bool valid = (n < Ntot);

    float gxv = 0.f, gyv = 0.f, gzv = 0.f;
    if (valid) {
        gxv = verts[3 * n + 0];
        gyv = verts[3 * n + 1];
        gzv = verts[3 * n + 2];
    }

    const int c4 = lane & 7;      // channel quad: channels 4*c4 .. 4*c4+3
    const int v4 = lane >> 3;     // vertex-in-group 0..3

    float* fw = fs + warp * (32 * 18);
    unsigned long long acc2[8];
    #pragma unroll
    for (int i = 0; i < 8; i++) acc2[i] = 0ull;

    const float SH = 0.0625f;   // 2^(STEPS+1-STEP)/128

    for (int k = 0; k < NK; k++) {
        // --- per-lane geometry for my own vertex ---
        const int ki = k / 9, kj = (k / 3) % 3, kl = k % 3;
        float gx = gxv + (float)(ki - 1) * SH;
        float gy = gyv + (float)(kj - 1) * SH;
        float gz = gzv + (float)(kl - 1) * SH;
        float px = fminf(fmaxf((gx + 1.f) * 63.5f, 0.f), 127.f);
        float py = fminf(fmaxf((gy + 1.f) * 63.5f, 0.f), 127.f);
        float pz = fminf(fmaxf((gz + 1.f) * 63.5f, 0.f), 127.f);
        const float fx = floorf(px), fy = floorf(py), fz = floorf(pz);
        const int ix = (int)fx, iy = (int)fy, iz = (int)fz;
        const float wx = px - fx, wy = py - fy, wz = pz - fz;
        const int base = iz * (DIM * DIM * C_CH) + iy * (DIM * C_CH) + ix * C_CH;
        const int sx = (ix < DIM - 1) ? C_CH : 0;
        const int sy = (iy < DIM - 1) ? DIM * C_CH : 0;
        const int sz = (iz < DIM - 1) ? DIM * DIM * C_CH : 0;

        // --- sampling: 4 vertex groups, float4 per (vertex, channel-quad) ---
        #pragma unroll
        for (int g4 = 0; g4 < 4; g4++) {
            const int src = g4 * 4 + v4;
            const int b   = __shfl_sync(0xffffffffu, base, src);
            const int sx4 = __shfl_sync(0xffffffffu, sx, src) >> 2;
            const int sy4 = __shfl_sync(0xffffffffu, sy, src) >> 2;
            const int sz4 = __shfl_sync(0xffffffffu, sz, src) >> 2;
            const float wxv = __shfl_sync(0xffffffffu, wx, src);
            const float wyv = __shfl_sync(0xffffffffu, wy, src);
            const float wzv = __shfl_sync(0xffffffffu, wz, src);

            const float4* p = reinterpret_cast<const float4*>(g_vol + b) + c4;
            const float4 f000 = __ldg(p);
            const float4 f001 = __ldg(p + sx4);
            const float4 f010 = __ldg(p + sy4);
            const float4 f011 = __ldg(p + sy4 + sx4);
            const float4 f100 = __ldg(p + sz4);
            const float4 f101 = __ldg(p + sz4 + sx4);
            const float4 f110 = __ldg(p + sz4 + sy4);
            const float4 f111 = __ldg(p + sz4 + sy4 + sx4);

            const float ax0 = 1.f - wxv, ay0 = 1.f - wyv, az0 = 1.f - wzv;
            const float c00 = az0 * ay0, c01 = az0 * wyv;
            const float c10 = wzv * ay0, c11 = wzv * wyv;
            const float w000 = c00 * ax0, w001 = c00 * wxv;
            const float w010 = c01 * ax0, w011 = c01 * wxv;
            const float w100 = c10 * ax0, w101 = c10 * wxv;
            const float w110 = c11 * ax0, w111 = c11 * wxv;

            float rx = f000.x * w000, ry = f000.y * w000,
                  rz = f000.z * w000, rw = f000.w * w000;
            rx = fmaf(f001.x, w001, rx); ry = fmaf(f001.y, w001, ry);
            rz = fmaf(f001.z, w001, rz); rw = fmaf(f001.w, w001, rw);
            rx = fmaf(f010.x, w010, rx); ry = fmaf(f010.y, w010, ry);
            rz = fmaf(f010.z, w010, rz); rw = fmaf(f010.w, w010, rw);
            rx = fmaf(f011.x, w011, rx); ry = fmaf(f011.y, w011, ry);
            rz = fmaf(f011.z, w011, rz); rw = fmaf(f011.w, w011, rw);
            rx = fmaf(f100.x, w100, rx); ry = fmaf(f100.y, w100, ry);
            rz = fmaf(f100.z, w100, rz); rw = fmaf(f100.w, w100, rw);
            rx = fmaf(f101.x, w101, rx); ry = fmaf(f101.y, w101, ry);
            rz = fmaf(f101.z, w101, rz); rw = fmaf(f101.w, w101, rw);
            rx = fmaf(f110.x, w110, rx); ry = fmaf(f110.y, w110, ry);
            rz = fmaf(f110.z, w110, rz); rw = fmaf(f110.w, w110, rw);
            rx = fmaf(f111.x, w111, rx); ry = fmaf(f111.y, w111, ry);
            rz = fmaf(f111.z, w111, rz); rw = fmaf(f111.w, w111, rw);

            const int col = g4 * 4 + v4;
            fw[(c4 * 4 + 0) * 18 + col] = rx;
            fw[(c4 * 4 + 1) * 18 + col] = ry;
            fw[(c4 * 4 + 2) * 18 + col] = rz;
            fw[(c4 * 4 + 3) * 18 + col] = rw;
        }
        __syncwarp();

        // --- reduction: acc[v][lane] += f[v][c] * G[k][c][lane] ---
        #pragma unroll 4
        for (int c = 0; c < 32; c++) {
            const float g = __ldg(&g_G[k * 1024 + c * 32 + lane]);
            unsigned long long g2;
            asm("mov.b64 %0, {%1, %1};" : "=l"(g2) : "r"(__float_as_uint(g)));
            const unsigned long long* fq =
                reinterpret_cast<const unsigned long long*>(fw + c * 18);
            #pragma unroll
            for (int v2 = 0; v2 < 8; v2++) {
                asm("fma.rn.f32x2 %0, %1, %2, %0;"
                    : "+l"(acc2[v2]) : "l"(fq[v2]), "l"(g2));
            }
        }
        __syncwarp();
    }

    const float bias = __ldg(&g_bias[lane]);
    #pragma unroll
    for (int v2 = 0; v2 < 8; v2++) {
        const float lo = __uint_as_float((unsigned)(acc2[v2] & 0xffffffffull));
        const float hi = __uint_as_float((unsigned)(acc2[v2] >> 32));
        const int na = n0 + 2 * v2, nb = na + 1;
        if (na < Ntot) out[na * C_CH + lane] = lo + bias;
        if (nb < Ntot) out[nb * C_CH + lane] = hi + bias;
    }
}

// ---------------------------------------------------------------------------
extern "C" void kernel_launch(void* const* d_in, const int* in_sizes, int n_in,
                              void* d_out, int out_size)
{
    const float* voxel = (const float*)d_in[0];
    const float* verts = (const float*)d_in[1];
    const int Ntot = in_sizes[1] / 3;

    prep1_kernel<<<27, 1024>>>(
        (const float*)d_in[2],   // w_d1
        (const float*)d_in[4],   // w_d2
        (const float*)d_in[10]); // conv_w

    prep2_kernel<<<1, 1024>>>(
        (const float*)d_in[4],   // w_d2
        (const float*)d_in[3],   // b_d1
        (const float*)d_in[5],   // b_d2
        (const float*)d_in[6],   // w_c1
        (const float*)d_in[7],   // b_c1
        (const float*)d_in[8],   // w_c2
        (const float*)d_in[9],   // b_c2
        (const float*)d_in[10],  // conv_w
        (const float*)d_in[11]); // conv_b

    dim3 tb(32, 8);
    dim3 tg(DIM / 32, DIM, DIM);
    transpose_kernel<<<tg, tb>>>(voxel);

    const int nTiles = (Ntot + 15) / 16;
    const int blocks = (nTiles + 7) / 8;
    main_kernel<<<blocks, 256>>>(verts, (float*)d_out, Ntot);
}

// round 3
// speedup vs baseline: 2.6237x; 1.0880x over previous
#include <cuda_runtime.h>
#include <cstdint>

#define C_CH 32
#define DIM  128
#define NK   27
#define VOL_ELEMS (C_CH * DIM * DIM * DIM)
#define NCELL 4096            // 16x16x16 cells of 8^3 voxels
#define PERM_MAX (1 << 18)

// Scratch (device globals: allocation-free per harness rules)
__device__ float g_vol[VOL_ELEMS];        // channel-last [z][y][x][c]
__device__ float g_G[NK * C_CH * C_CH];   // [k][j][o] folded weight tensor
__device__ float g_bias[C_CH];
__device__ int   g_hist[NCELL];
__device__ int   g_base[NCELL];
__device__ int   g_perm[PERM_MAX];

// ---------------------------------------------------------------------------
// Prep 1 (27 blocks): M[k][j][o] = sum_c conv_w[o,c,k]*Wd[c,j]
// ---------------------------------------------------------------------------
__global__ __launch_bounds__(1024) void prep1_kernel(
    const float* __restrict__ w_d1, const float* __restrict__ w_d2,
    const float* __restrict__ conv_w)
{
    __shared__ float Wds[1024];    // Wd[c][j]
    __shared__ float convs[1024];  // conv[c][o] for this k
    const int tid = threadIdx.x, k = blockIdx.x;
    const int o = tid & 31, j = tid >> 5;

    {   // Wd = w_d2 @ w_d1
        float s = 0.f;
        #pragma unroll
        for (int m = 0; m < 32; m++)
            s += w_d2[(tid >> 5) * 32 + m] * w_d1[m * 32 + (tid & 31)];
        Wds[tid] = s;
    }
    convs[tid] = conv_w[(o * 32 + (tid >> 5)) * 27 + k];
    __syncthreads();

    float acc = 0.f;
    #pragma unroll
    for (int c = 0; c < 32; c++)
        acc += convs[c * 32 + o] * Wds[c * 32 + j];
    g_G[k * 1024 + j * 32 + o] = acc;
}

// ---------------------------------------------------------------------------
// Prep 2 (1 block): center-tap correction on k=13 plane + fused bias.
// ---------------------------------------------------------------------------
__global__ __launch_bounds__(1024) void prep2_kernel(
    const float* __restrict__ w_d2, const float* __restrict__ b_d1,
    const float* __restrict__ b_d2,
    const float* __restrict__ w_c1, const float* __restrict__ b_c1,
    const float* __restrict__ w_c2, const float* __restrict__ b_c2,
    const float* __restrict__ conv_w, const float* __restrict__ conv_b)
{
    __shared__ float Wcs[1024], part[1024], bds[32], bcs[32];
    const int tid = threadIdx.x;
    const int o = tid & 31, j = tid >> 5;

    {   // Wc = w_c2 @ w_c1
        float s = 0.f;
        #pragma unroll
        for (int m = 0; m < 32; m++)
            s += w_c2[(tid >> 5) * 32 + m] * w_c1[m * 32 + (tid & 31)];
        Wcs[tid] = s;
    }
    if (tid < 32) {
        float sd = 0.f, sc = 0.f;
        #pragma unroll
        for (int m = 0; m < 32; m++) {
            sd += w_d2[tid * 32 + m] * b_d1[m];
            sc += w_c2[tid * 32 + m] * b_c1[m];
        }
        bds[tid] = sd + b_d2[tid];
        bcs[tid] = sc + b_c2[tid];
    }
    float rs = 0.f;
    #pragma unroll
    for (int k = 0; k < NK; k++)
        rs += conv_w[(o * 32 + j) * 27 + k];
    __syncthreads();

    part[j * 32 + o] = bds[j] * rs;

    float S = 0.f;
    #pragma unroll
    for (int k = 0; k < NK; k++) S += g_G[k * 1024 + tid];
    g_G[13 * 1024 + tid] += Wcs[o * 32 + j] - S;
    __syncthreads();

    if (tid < 32) {
        float a = 0.f;
        #pragma unroll
        for (int c = 0; c < 32; c++) a += part[c * 32 + tid];
        g_bias[tid] = a + conv_b[tid] + bcs[tid];
    }
}

// ---------------------------------------------------------------------------
// Transpose [C][D][H][W] -> channel-last [D][H][W][C], STG.128 stores.
// ---------------------------------------------------------------------------
__global__ __launch_bounds__(256) void transpose_kernel(const float* __restrict__ vin)
{
    __shared__ float tile[32][33];
    const int x0 = blockIdx.x * 32;
    const int y = blockIdx.y, z = blockIdx.z;
    const int tid = threadIdx.x;
    const int tx = tid & 31, ty = tid >> 5;  // load mapping: 32 x, 8 c-groups

    #pragma unroll
    for (int i = 0; i < 4; i++) {
        const int c = ty + 8 * i;
        tile[c][tx] = vin[(((size_t)c * DIM + z) * DIM + y) * DIM + x0 + tx];
    }
    __syncthreads();

    // store mapping: lane = (x-local within quad-group, channel-quad)
    const int q  = tid & 7;          // channel quad 0..7
    const int xl = (tid >> 3) & 3;   // x within group of 4
    const int xg = tid >> 5;         // group 0..7
    const size_t obase = ((size_t)z * DIM + y) * DIM + x0;
    const int xx = xg * 4 + xl;
    float4 v;
    v.x = tile[4 * q + 0][xx];
    v.y = tile[4 * q + 1][xx];
    v.z = tile[4 * q + 2][xx];
    v.w = tile[4 * q + 3][xx];
    reinterpret_cast<float4*>(g_vol + (obase + xx) * C_CH)[q] = v;
}

// ---------------------------------------------------------------------------
// Vertex binning: histogram -> scan -> scatter (cells of 8^3 voxels).
// ---------------------------------------------------------------------------
__device__ __forceinline__ int cell_of(float x, float y, float z)
{
    float px = fminf(fmaxf((x + 1.f) * 63.5f, 0.f), 127.f);
    float py = fminf(fmaxf((y + 1.f) * 63.5f, 0.f), 127.f);
    float pz = fminf(fmaxf((z + 1.f) * 63.5f, 0.f), 127.f);
    const int cx = ((int)px) >> 3, cy = ((int)py) >> 3, cz = ((int)pz) >> 3;
    return (cz << 8) | (cy << 4) | cx;
}

__global__ void zero_hist_kernel()
{
    const int t = blockIdx.x * blockDim.x + threadIdx.x;
    if (t < NCELL) { g_hist[t] = 0; g_base[t] = 0; }
}

__global__ void count_kernel(const float* __restrict__ verts, int Ntot)
{
    const int n = blockIdx.x * blockDim.x + threadIdx.x;
    if (n >= Ntot) return;
    atomicAdd(&g_hist[cell_of(verts[3 * n], verts[3 * n + 1], verts[3 * n + 2])], 1);
}

__global__ __launch_bounds__(1024) void scan_kernel()
{
    __shared__ int sh[1024];
    const int t = threadIdx.x;
    int h0 = g_hist[4 * t], h1 = g_hist[4 * t + 1],
        h2 = g_hist[4 * t + 2], h3 = g_hist[4 * t + 3];
    const int mysum = h0 + h1 + h2 + h3;
    sh[t] = mysum;
    __syncthreads();
    for (int off = 1; off < 1024; off <<= 1) {
        int v = (t >= off) ? sh[t - off] : 0;
        __syncthreads();
        sh[t] += v;
        __syncthreads();
    }
    int e = sh[t] - mysum;   // exclusive
    g_base[4 * t]     = e;
    g_base[4 * t + 1] = e + h0;
    g_base[4 * t + 2] = e + h0 + h1;
    g_base[4 * t + 3] = e + h0 + h1 + h2;
}

__global__ void scatter_kernel(const float* __restrict__ verts, int Ntot)
{
    const int n = blockIdx.x * blockDim.x + threadIdx.x;
    if (n >= Ntot) return;
    const int c = cell_of(verts[3 * n], verts[3 * n + 1], verts[3 * n + 2]);
    const int pos = atomicAdd(&g_base[c], 1);
    g_perm[pos] = n;
}

// ---------------------------------------------------------------------------
// Fused sample + GEMM over permuted (spatially sorted) vertices.
// One warp = 16 vertices. Sampling lane = (vertex-quad, channel-quad), float4
// corner loads; reduction lane = output channel, packed fma.rn.f32x2.
// ---------------------------------------------------------------------------
__global__ __launch_bounds__(256, 4) void main_kernel(
    const float* __restrict__ verts, float* __restrict__ out, int Ntot)
{
    __shared__ float fs[8 * 32 * 18];
    const int warp = threadIdx.x >> 5, lane = threadIdx.x & 31;
    const int nTiles = (Ntot + 15) >> 4;
    const int tile = blockIdx.x * 8 + warp;
    if (tile >= nTiles) return;

    const int n0 = tile * 16;
    const int v = lane & 15;
    const int idx = n0 + v;
    const bool valid = (idx < Ntot);
    const int n = valid ? g_perm[idx] : 0;

    float gxv = 0.f, gyv = 0.f, gzv = 0.f;
    if (valid) {
        gxv = verts[3 * n + 0];
        gyv = verts[3 * n + 1];
        gzv = verts[3 * n + 2];
    }

    const int c4 = lane & 7;
    const int v4 = lane >> 3;

    float* fw = fs + warp * (32 * 18);
    unsigned long long acc2[8];
    #pragma unroll
    for (int i = 0; i < 8; i++) acc2[i] = 0ull;

    const float SH = 0.0625f;

    for (int k = 0; k < NK; k++) {
        const int ki = k / 9, kj = (k / 3) % 3, kl = k % 3;
        float gx = gxv + (float)(ki - 1) * SH;
        float gy = gyv + (float)(kj - 1) * SH;
        float gz = gzv + (float)(kl - 1) * SH;
        float px = fminf(fmaxf((gx + 1.f) * 63.5f, 0.f), 127.f);
        float py = fminf(fmaxf((gy + 1.f) * 63.5f, 0.f), 127.f);
        float pz = fminf(fmaxf((gz + 1.f) * 63.5f, 0.f), 127.f);
        const float fx = floorf(px), fy = floorf(py), fz = floorf(pz);
        const int ix = (int)fx, iy = (int)fy, iz = (int)fz;
        const float wx = px - fx, wy = py - fy, wz = pz - fz;
        const int base = iz * (DIM * DIM * C_CH) + iy * (DIM * C_CH) + ix * C_CH;
        const int sx = (ix < DIM - 1) ? C_CH : 0;
        const int sy = (iy < DIM - 1) ? DIM * C_CH : 0;
        const int sz = (iz < DIM - 1) ? DIM * DIM * C_CH : 0;

        #pragma unroll
        for (int g4 = 0; g4 < 4; g4++) {
            const int src = g4 * 4 + v4;
            const int b   = __shfl_sync(0xffffffffu, base, src);
            const int sx4 = __shfl_sync(0xffffffffu, sx, src) >> 2;
            const int sy4 = __shfl_sync(0xffffffffu, sy, src) >> 2;
            const int sz4 = __shfl_sync(0xffffffffu, sz, src) >> 2;
            const float wxv = __shfl_sync(0xffffffffu, wx, src);
            const float wyv = __shfl_sync(0xffffffffu, wy, src);
            const float wzv = __shfl_sync(0xffffffffu, wz, src);

            const float4* p = reinterpret_cast<const float4*>(g_vol + b) + c4;
            const float4 f000 = __ldg(p);
            const float4 f001 = __ldg(p + sx4);
            const float4 f010 = __ldg(p + sy4);
            const float4 f011 = __ldg(p + sy4 + sx4);
            const float4 f100 = __ldg(p + sz4);
            const float4 f101 = __ldg(p + sz4 + sx4);
            const float4 f110 = __ldg(p + sz4 + sy4);
            const float4 f111 = __ldg(p + sz4 + sy4 + sx4);

            const float ax0 = 1.f - wxv, ay0 = 1.f - wyv, az0 = 1.f - wzv;
            const float c00 = az0 * ay0, c01 = az0 * wyv;
            const float c10 = wzv * ay0, c11 = wzv * wyv;
            const float w000 = c00 * ax0, w001 = c00 * wxv;
            const float w010 = c01 * ax0, w011 = c01 * wxv;
            const float w100 = c10 * ax0, w101 = c10 * wxv;
            const float w110 = c11 * ax0, w111 = c11 * wxv;

            float rx = f000.x * w000, ry = f000.y * w000,
                  rz = f000.z * w000, rw = f000.w * w000;
            rx = fmaf(f001.x, w001, rx); ry = fmaf(f001.y, w001, ry);
            rz = fmaf(f001.z, w001, rz); rw = fmaf(f001.w, w001, rw);
            rx = fmaf(f010.x, w010, rx); ry = fmaf(f010.y, w010, ry);
            rz = fmaf(f010.z, w010, rz); rw = fmaf(f010.w, w010, rw);
            rx = fmaf(f011.x, w011, rx); ry = fmaf(f011.y, w011, ry);
            rz = fmaf(f011.z, w011, rz); rw = fmaf(f011.w, w011, rw);
            rx = fmaf(f100.x, w100, rx); ry = fmaf(f100.y, w100, ry);
            rz = fmaf(f100.z, w100, rz); rw = fmaf(f100.w, w100, rw);
            rx = fmaf(f101.x, w101, rx); ry = fmaf(f101.y, w101, ry);
            rz = fmaf(f101.z, w101, rz); rw = fmaf(f101.w, w101, rw);
            rx = fmaf(f110.x, w110, rx); ry = fmaf(f110.y, w110, ry);
            rz = fmaf(f110.z, w110, rz); rw = fmaf(f110.w, w110, rw);
            rx = fmaf(f111.x, w111, rx); ry = fmaf(f111.y, w111, ry);
            rz = fmaf(f111.z, w111, rz); rw = fmaf(f111.w, w111, rw);

            const int col = g4 * 4 + v4;
            fw[(c4 * 4 + 0) * 18 + col] = rx;
            fw[(c4 * 4 + 1) * 18 + col] = ry;
            fw[(c4 * 4 + 2) * 18 + col] = rz;
            fw[(c4 * 4 + 3) * 18 + col] = rw;
        }
        __syncwarp();

        #pragma unroll 4
        for (int c = 0; c < 32; c++) {
            const float g = __ldg(&g_G[k * 1024 + c * 32 + lane]);
            unsigned long long g2;
            asm("mov.b64 %0, {%1, %1};" : "=l"(g2) : "r"(__float_as_uint(g)));
            const unsigned long long* fq =
                reinterpret_cast<const unsigned long long*>(fw + c * 18);
            #pragma unroll
            for (int v2 = 0; v2 < 8; v2++) {
                asm("fma.rn.f32x2 %0, %1, %2, %0;"
                    : "+l"(acc2[v2]) : "l"(fq[v2]), "l"(g2));
            }
        }
        __syncwarp();
    }

    const float bias = __ldg(&g_bias[lane]);
    #pragma unroll
    for (int v2 = 0; v2 < 8; v2++) {
        const float lo = __uint_as_float((unsigned)(acc2[v2] & 0xffffffffull));
        const float hi = __uint_as_float((unsigned)(acc2[v2] >> 32));
        const int ia = n0 + 2 * v2, ib = ia + 1;
        if (ia < Ntot) out[g_perm[ia] * C_CH + lane] = lo + bias;
        if (ib < Ntot) out[g_perm[ib] * C_CH + lane] = hi + bias;
    }
}

// ---------------------------------------------------------------------------
extern "C" void kernel_launch(void* const* d_in, const int* in_sizes, int n_in,
                              void* d_out, int out_size)
{
    const float* voxel = (const float*)d_in[0];
    const float* verts = (const float*)d_in[1];
    const int Ntot = in_sizes[1] / 3;

    prep1_kernel<<<27, 1024>>>(
        (const float*)d_in[2], (const float*)d_in[4], (const float*)d_in[10]);

    prep2_kernel<<<1, 1024>>>(
        (const float*)d_in[4], (const float*)d_in[3], (const float*)d_in[5],
        (const float*)d_in[6], (const float*)d_in[7], (const float*)d_in[8],
        (const float*)d_in[9], (const float*)d_in[10], (const float*)d_in[11]);

    // vertex spatial binning
    zero_hist_kernel<<<(NCELL + 255) / 256, 256>>>();
    count_kernel<<<(Ntot + 255) / 256, 256>>>(verts, Ntot);
    scan_kernel<<<1, 1024>>>();
    scatter_kernel<<<(Ntot + 255) / 256, 256>>>(verts, Ntot);

    dim3 tb(256);
    dim3 tg(DIM / 32, DIM, DIM);
    transpose_kernel<<<tg, tb>>>(voxel);

    const int nTiles = (Ntot + 15) / 16;
    const int blocks = (nTiles + 7) / 8;
    main_kernel<<<blocks, 256>>>(verts, (float*)d_out, Ntot);
}